// round 12
// baseline (speedup 1.0000x reference)
#include <cuda_runtime.h>
#include <cuda_fp16.h>
#include <cstdint>

#define DIM 2048
constexpr int MBIG  = 16384;           // 4*4096 tokens
constexpr int BM = 128, BN = 128, BK = 64;
constexpr int STAGES = 3;
constexpr int THREADS = 256;
constexpr int NITER = DIM / BK;        // 32 k-chunks
constexpr int STG_A = BM * 128;        // 16384 B (128 rows x 128B)
constexpr int STG_B = BK * 256;        // 16384 B (64 rows x 256B)
constexpr int STGB  = STG_A + STG_B;   // 32768 B per stage
constexpr int SMEM_TOTAL = STAGES * STGB;  // 98304 B  (2 CTAs/SM)

// ---------------- device scratch (no allocs allowed) ----------------
__device__ __half g_Ah[(size_t)DIM * DIM];   // fp16(A)
__device__ __half g_W [(size_t)DIM * DIM];   // fp16(I + 2A + A^2), [k][n]
__device__ __half g_Xh[(size_t)MBIG * DIM];  // fp16(X)

// ---------------- static stream/event for graph fork-join ----------------
struct GInit {
    cudaStream_t s2;
    cudaEvent_t eFork, eJoin;
    GInit() {
        cudaStreamCreateWithFlags(&s2, cudaStreamNonBlocking);
        cudaEventCreateWithFlags(&eFork, cudaEventDisableTiming);
        cudaEventCreateWithFlags(&eJoin, cudaEventDisableTiming);
    }
};
static GInit g_si;

// ---------------- PTX helpers ----------------
__device__ __forceinline__ uint32_t smem_u32(const void* p) {
    uint32_t a;
    asm("{ .reg .u64 t; cvta.to.shared.u64 t, %1; cvt.u32.u64 %0, t; }" : "=r"(a) : "l"(p));
    return a;
}
#define CP_ASYNC_16(dst, src) \
    asm volatile("cp.async.cg.shared.global [%0], [%1], 16;" :: "r"(dst), "l"(src) : "memory")
#define CP_COMMIT() asm volatile("cp.async.commit_group;" ::: "memory")
#define CP_WAIT_1() asm volatile("cp.async.wait_group 1;" ::: "memory")
#define CP_WAIT_0() asm volatile("cp.async.wait_group 0;" ::: "memory")

__device__ __forceinline__ void ldsm_x4(uint32_t* r, uint32_t addr) {
    asm volatile("ldmatrix.sync.aligned.m8n8.x4.shared.b16 {%0,%1,%2,%3}, [%4];"
                 : "=r"(r[0]), "=r"(r[1]), "=r"(r[2]), "=r"(r[3]) : "r"(addr));
}
__device__ __forceinline__ void ldsm_x4t(uint32_t* r, uint32_t addr) {
    asm volatile("ldmatrix.sync.aligned.m8n8.x4.trans.shared.b16 {%0,%1,%2,%3}, [%4];"
                 : "=r"(r[0]), "=r"(r[1]), "=r"(r[2]), "=r"(r[3]) : "r"(addr));
}
__device__ __forceinline__ void mma16816(float* c, const uint32_t* a, const uint32_t* b) {
    asm volatile(
        "mma.sync.aligned.m16n8k16.row.col.f32.f16.f16.f32 "
        "{%0,%1,%2,%3}, {%4,%5,%6,%7}, {%8,%9}, {%0,%1,%2,%3};"
        : "+f"(c[0]), "+f"(c[1]), "+f"(c[2]), "+f"(c[3])
        : "r"(a[0]), "r"(a[1]), "r"(a[2]), "r"(a[3]), "r"(b[0]), "r"(b[1]));
}

// ---------------- build kernels ----------------
__device__ __forceinline__ float skew_entry(const float* __restrict__ angles, int i, int j) {
    if (i == j) return 0.0f;
    if (i < j)  return  angles[i * (2 * DIM - i - 1) / 2 + (j - i - 1)];
    return -angles[j * (2 * DIM - j - 1) / 2 + (i - j - 1)];
}

__global__ void build_Ah(const float* __restrict__ angles) {
    int j = blockIdx.x * blockDim.x + threadIdx.x;
    int i = blockIdx.y;
    g_Ah[(size_t)i * DIM + j] = __float2half(skew_entry(angles, i, j));
}

__global__ void build_Xh(const float* __restrict__ x) {
    size_t f = (size_t)blockIdx.x * blockDim.x + threadIdx.x;  // float4 index
    float4 v = *(const float4*)(x + f * 4);
    __half2 h0 = __floats2half2_rn(v.x, v.y);
    __half2 h1 = __floats2half2_rn(v.z, v.w);
    *(__half2*)(&g_Xh[f * 4])     = h0;
    *(__half2*)(&g_Xh[f * 4 + 2]) = h1;
}

// ---------------- fp16 HMMA GEMM ----------------
// acc[m,n] = sum_k Ag[m,k] * Bg[k,n]
// WEPI=false: outf[m,n] = acc + bias[n]
// WEPI=true : g_W[m,n]  = fp16(acc + 2*A[m,n] + (m==n))   (A from angles)
__device__ __forceinline__ void load_tile(
    uint32_t sA, uint32_t sB,
    const __half* __restrict__ Ag, const __half* __restrict__ Bg,
    int m0, int n0, int k0, int tid)
{
    const char* ap = (const char*)(Ag + (size_t)m0 * DIM + k0);
    #pragma unroll
    for (int it = 0; it < 4; it++) {            // A: 128 rows x 8 chunks(16B)
        int idx = tid + it * THREADS;
        int m = idx >> 3, c = idx & 7;
        CP_ASYNC_16(sA + m * 128 + ((c * 16) ^ ((m & 7) * 16)),
                    ap + (size_t)m * (DIM * 2) + c * 16);
    }
    const char* bp = (const char*)(Bg + (size_t)k0 * DIM + n0);
    #pragma unroll
    for (int it = 0; it < 4; it++) {            // B: 64 rows x 16 chunks(16B)
        int idx = tid + it * THREADS;
        int k = idx >> 4, c = idx & 15;
        CP_ASYNC_16(sB + k * 256 + ((c * 16) ^ ((k & 7) * 16)),
                    bp + (size_t)k * (DIM * 2) + c * 16);
    }
}

template <bool WEPI>
__global__ __launch_bounds__(THREADS, 2)
void hgemm(const __half* __restrict__ Ag, const __half* __restrict__ Bg,
           float* __restrict__ outf, const float* __restrict__ angles,
           const float* __restrict__ bias)
{
    extern __shared__ char smem[];
    uint32_t sb = smem_u32(smem);
    int tid = threadIdx.x, lane = tid & 31, wid = tid >> 5;
    int wm = (wid >> 2) * 64;     // warp row offset within CTA (0 or 64)
    int wn = (wid & 3) * 32;      // warp col offset within CTA (0..96)
    int m0 = blockIdx.y * BM, n0 = blockIdx.x * BN;

    float acc[4][4][4];
    #pragma unroll
    for (int i = 0; i < 4; i++)
        #pragma unroll
        for (int j = 0; j < 4; j++)
            #pragma unroll
            for (int q = 0; q < 4; q++)
                acc[i][j][q] = 0.0f;

    // prologue: stages 0..STAGES-2
    #pragma unroll
    for (int s = 0; s < STAGES - 1; s++) {
        uint32_t sA = sb + s * STGB;
        load_tile(sA, sA + STG_A, Ag, Bg, m0, n0, s * BK, tid);
        CP_COMMIT();
    }

    for (int c = 0; c < NITER; c++) {
        int st = c % STAGES;
        uint32_t sA = sb + st * STGB;
        uint32_t sB = sA + STG_A;

        if (c + 1 < NITER) { CP_WAIT_1(); } else { CP_WAIT_0(); }
        __syncthreads();

        if (c + STAGES - 1 < NITER) {
            int st2 = (c + STAGES - 1) % STAGES;
            uint32_t nA = sb + st2 * STGB;
            load_tile(nA, nA + STG_A, Ag, Bg, m0, n0, (c + STAGES - 1) * BK, tid);
            CP_COMMIT();
        }

        #pragma unroll
        for (int ks = 0; ks < 4; ks++) {        // 4 x k16 within BK=64
            uint32_t a[4][4];
            uint32_t b[4][2];
            // A frags: m16k16 via ldmatrix.x4
            {
                int rbase = wm + (lane & 15);
                int kb = ks * 32 + (lane >> 4) * 16;
                #pragma unroll
                for (int mi = 0; mi < 4; mi++) {
                    int r = rbase + mi * 16;
                    ldsm_x4(a[mi], sA + r * 128 + (kb ^ ((r & 7) * 16)));
                }
            }
            // B frags: k16n16 via ldmatrix.x4.trans -> two n8 frags each
            {
                int grp = lane >> 3;
                int kk = ks * 16 + (grp & 1) * 8 + (lane & 7);
                int nbase = (wn + (grp >> 1) * 8) * 2;
                uint32_t rowa = sB + kk * 256;
                int kx = (kk & 7) * 16;
                #pragma unroll
                for (int nj = 0; nj < 2; nj++) {
                    uint32_t r4[4];
                    ldsm_x4t(r4, rowa + ((nbase + nj * 32) ^ kx));
                    b[nj * 2][0] = r4[0]; b[nj * 2][1] = r4[1];
                    b[nj * 2 + 1][0] = r4[2]; b[nj * 2 + 1][1] = r4[3];
                }
            }
            #pragma unroll
            for (int mi = 0; mi < 4; mi++)
                #pragma unroll
                for (int nf = 0; nf < 4; nf++)
                    mma16816(acc[mi][nf], a[mi], b[nf]);
        }
    }

    // epilogue
    int rbase = m0 + wm + (lane >> 2);
    int cbase = n0 + wn + (lane & 3) * 2;
    #pragma unroll
    for (int mi = 0; mi < 4; mi++) {
        #pragma unroll
        for (int nf = 0; nf < 4; nf++) {
            int r = rbase + mi * 16;
            int col = cbase + nf * 8;
            if (WEPI) {
                // W[r][col] = acc + 2*A[r][col] + (r==col), fp16
                #pragma unroll
                for (int h = 0; h < 2; h++) {
                    int rr = r + h * 8;
                    float w0 = acc[mi][nf][h * 2 + 0]
                             + 2.0f * skew_entry(angles, rr, col)
                             + (rr == col ? 1.0f : 0.0f);
                    float w1 = acc[mi][nf][h * 2 + 1]
                             + 2.0f * skew_entry(angles, rr, col + 1)
                             + (rr == col + 1 ? 1.0f : 0.0f);
                    *(__half2*)(&g_W[(size_t)rr * DIM + col]) =
                        __floats2half2_rn(w0, w1);
                }
            } else {
                float2 bv = *(const float2*)(bias + col);
                float2 v0 = make_float2(acc[mi][nf][0] + bv.x, acc[mi][nf][1] + bv.y);
                float2 v1 = make_float2(acc[mi][nf][2] + bv.x, acc[mi][nf][3] + bv.y);
                *(float2*)(outf + (size_t)r * DIM + col) = v0;
                *(float2*)(outf + (size_t)(r + 8) * DIM + col) = v1;
            }
        }
    }
}

// ---------------- launch ----------------
extern "C" void kernel_launch(void* const* d_in, const int* in_sizes, int n_in,
                              void* d_out, int out_size) {
    const float* x      = (const float*)d_in[0];   // [4,4096,2048]
    const float* angles = (const float*)d_in[1];
    const float* bias   = (const float*)d_in[2];
    float* out          = (float*)d_out;

    cudaFuncSetAttribute(hgemm<true>,  cudaFuncAttributeMaxDynamicSharedMemorySize, SMEM_TOTAL);
    cudaFuncSetAttribute(hgemm<false>, cudaFuncAttributeMaxDynamicSharedMemorySize, SMEM_TOTAL);

    __half *Ah, *W, *Xh;
    cudaGetSymbolAddress((void**)&Ah, g_Ah);
    cudaGetSymbolAddress((void**)&W,  g_W);
    cudaGetSymbolAddress((void**)&Xh, g_Xh);

    // Fork: branch 2 (side stream) converts X -> fp16 concurrently with the
    // W chain (build_Ah -> hgemm<1>) on the main stream.
    cudaEventRecord(g_si.eFork, 0);
    cudaStreamWaitEvent(g_si.s2, g_si.eFork, 0);
    build_Xh<<<(size_t)MBIG * DIM / 4 / 256, 256, 0, g_si.s2>>>(x);
    cudaEventRecord(g_si.eJoin, g_si.s2);

    // Branch 1 (main stream): W = I + 2A + A@A
    build_Ah<<<dim3(DIM / 256, DIM), 256>>>(angles);
    hgemm<true><<<dim3(DIM / BN, DIM / BM), THREADS, SMEM_TOTAL>>>(
        Ah, Ah, nullptr, angles, nullptr);

    // Join, then big GEMM: out = Xh @ W + bias
    cudaStreamWaitEvent(0, g_si.eJoin, 0);
    hgemm<false><<<dim3(DIM / BN, MBIG / BM), THREADS, SMEM_TOTAL>>>(
        Xh, W, out, nullptr, bias);
}

// round 16
// speedup vs baseline: 1.0025x; 1.0025x over previous
#include <cuda_runtime.h>
#include <cuda_fp16.h>
#include <cstdint>

#define DIM 2048
constexpr int MBIG  = 16384;           // 4*4096 tokens
constexpr int BM = 128, BN = 128, BK = 64;
constexpr int STAGES = 3;
constexpr int THREADS = 256;
constexpr int NITER = DIM / BK;        // 32 k-chunks
constexpr int STG_A = BM * 128;        // 16384 B (128 rows x 128B)
constexpr int STG_B = BK * 256;        // 16384 B (64 rows x 256B)
constexpr int STGB  = STG_A + STG_B;   // 32768 B per stage
constexpr int SMEM_TOTAL = STAGES * STGB;  // 98304 B  (2 CTAs/SM)
constexpr int GEMM_NX = DIM / BN;      // 16 GEMM blocks in x for hgemm<1>
constexpr int NCONV = 256;             // converter blocks fused into hgemm<1>
constexpr size_t XFLOATS = (size_t)MBIG * DIM;            // 33,554,432
constexpr size_t CONV_F4_PER_BLK = XFLOATS / 4 / NCONV;   // 32768 float4
constexpr int CONV_ITERS = (int)(CONV_F4_PER_BLK / THREADS);  // 128

// ---------------- device scratch (no allocs allowed) ----------------
__device__ __half g_Ah[(size_t)DIM * DIM];   // fp16(A)
__device__ __half g_W [(size_t)DIM * DIM];   // fp16(I + 2A + A^2), [k][n]
__device__ __half g_Xh[(size_t)MBIG * DIM];  // fp16(X)

// ---------------- PTX helpers ----------------
__device__ __forceinline__ uint32_t smem_u32(const void* p) {
    uint32_t a;
    asm("{ .reg .u64 t; cvta.to.shared.u64 t, %1; cvt.u32.u64 %0, t; }" : "=r"(a) : "l"(p));
    return a;
}
#define CP_ASYNC_16(dst, src) \
    asm volatile("cp.async.cg.shared.global [%0], [%1], 16;" :: "r"(dst), "l"(src) : "memory")
#define CP_COMMIT() asm volatile("cp.async.commit_group;" ::: "memory")
#define CP_WAIT_1() asm volatile("cp.async.wait_group 1;" ::: "memory")
#define CP_WAIT_0() asm volatile("cp.async.wait_group 0;" ::: "memory")

__device__ __forceinline__ void ldsm_x4(uint32_t* r, uint32_t addr) {
    asm volatile("ldmatrix.sync.aligned.m8n8.x4.shared.b16 {%0,%1,%2,%3}, [%4];"
                 : "=r"(r[0]), "=r"(r[1]), "=r"(r[2]), "=r"(r[3]) : "r"(addr));
}
__device__ __forceinline__ void ldsm_x4t(uint32_t* r, uint32_t addr) {
    asm volatile("ldmatrix.sync.aligned.m8n8.x4.trans.shared.b16 {%0,%1,%2,%3}, [%4];"
                 : "=r"(r[0]), "=r"(r[1]), "=r"(r[2]), "=r"(r[3]) : "r"(addr));
}
__device__ __forceinline__ void mma16816(float* c, const uint32_t* a, const uint32_t* b) {
    asm volatile(
        "mma.sync.aligned.m16n8k16.row.col.f32.f16.f16.f32 "
        "{%0,%1,%2,%3}, {%4,%5,%6,%7}, {%8,%9}, {%0,%1,%2,%3};"
        : "+f"(c[0]), "+f"(c[1]), "+f"(c[2]), "+f"(c[3])
        : "r"(a[0]), "r"(a[1]), "r"(a[2]), "r"(a[3]), "r"(b[0]), "r"(b[1]));
}

// ---------------- build kernels ----------------
__device__ __forceinline__ float skew_entry(const float* __restrict__ angles, int i, int j) {
    if (i == j) return 0.0f;
    if (i < j)  return  angles[i * (2 * DIM - i - 1) / 2 + (j - i - 1)];
    return -angles[j * (2 * DIM - j - 1) / 2 + (i - j - 1)];
}

// Upper-triangle-block version: block (bi,bj) with bi<=bj computes the 32x32
// tile from coalesced angles reads and writes both the tile and its negated
// transpose (through an smem tile). Blocks with bi>bj exit immediately.
__global__ void build_Ah_sym(const float* __restrict__ angles) {
    int bi = blockIdx.y, bj = blockIdx.x;
    if (bi > bj) return;
    __shared__ float tile[32][33];
    int t = threadIdx.x;
    int tr = t >> 3;            // 0..31 row within tile
    int tc = (t & 7) * 4;       // 0..28 col group within tile
    int i0 = bi * 32, j0 = bj * 32;
    int i = i0 + tr;
    float v[4];
    #pragma unroll
    for (int q = 0; q < 4; q++) {
        int j = j0 + tc + q;
        v[q] = skew_entry(angles, i, j);   // bi<bj: all coalesced upper reads
        tile[tr][tc + q] = v[q];
    }
    // direct store (row-major, coalesced 8B per thread)
    {
        __half2 h0 = __floats2half2_rn(v[0], v[1]);
        __half2 h1 = __floats2half2_rn(v[2], v[3]);
        __half2* p = (__half2*)&g_Ah[(size_t)i * DIM + j0 + tc];
        p[0] = h0; p[1] = h1;
    }
    __syncthreads();
    // transposed store: g_Ah[j][i] = -tile[i-i0][j-j0]
    {
        int jr = j0 + tr;                // output row
        float w[4];
        #pragma unroll
        for (int q = 0; q < 4; q++)
            w[q] = -tile[tc + q][tr];
        __half2 h0 = __floats2half2_rn(w[0], w[1]);
        __half2 h1 = __floats2half2_rn(w[2], w[3]);
        __half2* p = (__half2*)&g_Ah[(size_t)jr * DIM + i0 + tc];
        p[0] = h0; p[1] = h1;
    }
}

// ---------------- fp16 HMMA GEMM ----------------
// acc[m,n] = sum_k Ag[m,k] * Bg[k,n]
// WEPI=false: outf[m,n] = acc + bias[n]
// WEPI=true : g_W[m,n]  = fp16(acc + 2*A[m,n] + (m==n))   (A from angles)
//             + fused converter CTAs (blockIdx.x >= GEMM_NX) doing X -> fp16
__device__ __forceinline__ void load_tile(
    uint32_t sA, uint32_t sB,
    const __half* __restrict__ Ag, const __half* __restrict__ Bg,
    int m0, int n0, int k0, int tid)
{
    const char* ap = (const char*)(Ag + (size_t)m0 * DIM + k0);
    #pragma unroll
    for (int it = 0; it < 4; it++) {            // A: 128 rows x 8 chunks(16B)
        int idx = tid + it * THREADS;
        int m = idx >> 3, c = idx & 7;
        CP_ASYNC_16(sA + m * 128 + ((c * 16) ^ ((m & 7) * 16)),
                    ap + (size_t)m * (DIM * 2) + c * 16);
    }
    const char* bp = (const char*)(Bg + (size_t)k0 * DIM + n0);
    #pragma unroll
    for (int it = 0; it < 4; it++) {            // B: 64 rows x 16 chunks(16B)
        int idx = tid + it * THREADS;
        int k = idx >> 4, c = idx & 15;
        CP_ASYNC_16(sB + k * 256 + ((c * 16) ^ ((k & 7) * 16)),
                    bp + (size_t)k * (DIM * 2) + c * 16);
    }
}

template <bool WEPI>
__global__ __launch_bounds__(THREADS, 2)
void hgemm(const __half* __restrict__ Ag, const __half* __restrict__ Bg,
           float* __restrict__ outf, const float* __restrict__ angles,
           const float* __restrict__ bias, const float* __restrict__ xsrc)
{
    // ---- fused X->fp16 converter CTAs (only in the WEPI=true launch) ----
    if (WEPI && blockIdx.x >= GEMM_NX) {
        int cid = (blockIdx.x - GEMM_NX) * gridDim.y + blockIdx.y;  // 0..255
        const float4* src = (const float4*)xsrc + (size_t)cid * CONV_F4_PER_BLK;
        __half2* dst = (__half2*)&g_Xh[(size_t)cid * CONV_F4_PER_BLK * 4];
        int tid = threadIdx.x;
        #pragma unroll 4
        for (int it = 0; it < CONV_ITERS; it++) {
            size_t idx = (size_t)it * THREADS + tid;
            float4 v = src[idx];
            dst[idx * 2]     = __floats2half2_rn(v.x, v.y);
            dst[idx * 2 + 1] = __floats2half2_rn(v.z, v.w);
        }
        return;
    }

    extern __shared__ char smem[];
    uint32_t sb = smem_u32(smem);
    int tid = threadIdx.x, lane = tid & 31, wid = tid >> 5;
    int wm = (wid >> 2) * 64;     // warp row offset within CTA (0 or 64)
    int wn = (wid & 3) * 32;      // warp col offset within CTA (0..96)
    int m0 = blockIdx.y * BM, n0 = blockIdx.x * BN;

    float acc[4][4][4];
    #pragma unroll
    for (int i = 0; i < 4; i++)
        #pragma unroll
        for (int j = 0; j < 4; j++)
            #pragma unroll
            for (int q = 0; q < 4; q++)
                acc[i][j][q] = 0.0f;

    // prologue: stages 0..STAGES-2
    #pragma unroll
    for (int s = 0; s < STAGES - 1; s++) {
        uint32_t sA = sb + s * STGB;
        load_tile(sA, sA + STG_A, Ag, Bg, m0, n0, s * BK, tid);
        CP_COMMIT();
    }

    for (int c = 0; c < NITER; c++) {
        int st = c % STAGES;
        uint32_t sA = sb + st * STGB;
        uint32_t sB = sA + STG_A;

        if (c + 1 < NITER) { CP_WAIT_1(); } else { CP_WAIT_0(); }
        __syncthreads();

        if (c + STAGES - 1 < NITER) {
            int st2 = (c + STAGES - 1) % STAGES;
            uint32_t nA = sb + st2 * STGB;
            load_tile(nA, nA + STG_A, Ag, Bg, m0, n0, (c + STAGES - 1) * BK, tid);
            CP_COMMIT();
        }

        #pragma unroll
        for (int ks = 0; ks < 4; ks++) {        // 4 x k16 within BK=64
            uint32_t a[4][4];
            uint32_t b[4][2];
            // A frags: m16k16 via ldmatrix.x4
            {
                int rbase = wm + (lane & 15);
                int kb = ks * 32 + (lane >> 4) * 16;
                #pragma unroll
                for (int mi = 0; mi < 4; mi++) {
                    int r = rbase + mi * 16;
                    ldsm_x4(a[mi], sA + r * 128 + (kb ^ ((r & 7) * 16)));
                }
            }
            // B frags: k16n16 via ldmatrix.x4.trans -> two n8 frags each
            {
                int grp = lane >> 3;
                int kk = ks * 16 + (grp & 1) * 8 + (lane & 7);
                int nbase = (wn + (grp >> 1) * 8) * 2;
                uint32_t rowa = sB + kk * 256;
                int kx = (kk & 7) * 16;
                #pragma unroll
                for (int nj = 0; nj < 2; nj++) {
                    uint32_t r4[4];
                    ldsm_x4t(r4, rowa + ((nbase + nj * 32) ^ kx));
                    b[nj * 2][0] = r4[0]; b[nj * 2][1] = r4[1];
                    b[nj * 2 + 1][0] = r4[2]; b[nj * 2 + 1][1] = r4[3];
                }
            }
            #pragma unroll
            for (int mi = 0; mi < 4; mi++)
                #pragma unroll
                for (int nf = 0; nf < 4; nf++)
                    mma16816(acc[mi][nf], a[mi], b[nf]);
        }
    }

    // epilogue
    int rbase = m0 + wm + (lane >> 2);
    int cbase = n0 + wn + (lane & 3) * 2;
    #pragma unroll
    for (int mi = 0; mi < 4; mi++) {
        #pragma unroll
        for (int nf = 0; nf < 4; nf++) {
            int r = rbase + mi * 16;
            int col = cbase + nf * 8;
            if (WEPI) {
                // W[r][col] = acc + 2*A[r][col] + (r==col), fp16
                #pragma unroll
                for (int h = 0; h < 2; h++) {
                    int rr = r + h * 8;
                    float w0 = acc[mi][nf][h * 2 + 0]
                             + 2.0f * skew_entry(angles, rr, col)
                             + (rr == col ? 1.0f : 0.0f);
                    float w1 = acc[mi][nf][h * 2 + 1]
                             + 2.0f * skew_entry(angles, rr, col + 1)
                             + (rr == col + 1 ? 1.0f : 0.0f);
                    *(__half2*)(&g_W[(size_t)rr * DIM + col]) =
                        __floats2half2_rn(w0, w1);
                }
            } else {
                float2 bv = *(const float2*)(bias + col);
                float2 v0 = make_float2(acc[mi][nf][0] + bv.x, acc[mi][nf][1] + bv.y);
                float2 v1 = make_float2(acc[mi][nf][2] + bv.x, acc[mi][nf][3] + bv.y);
                *(float2*)(outf + (size_t)r * DIM + col) = v0;
                *(float2*)(outf + (size_t)(r + 8) * DIM + col) = v1;
            }
        }
    }
}

// ---------------- launch ----------------
extern "C" void kernel_launch(void* const* d_in, const int* in_sizes, int n_in,
                              void* d_out, int out_size) {
    const float* x      = (const float*)d_in[0];   // [4,4096,2048]
    const float* angles = (const float*)d_in[1];
    const float* bias   = (const float*)d_in[2];
    float* out          = (float*)d_out;

    cudaFuncSetAttribute(hgemm<true>,  cudaFuncAttributeMaxDynamicSharedMemorySize, SMEM_TOTAL);
    cudaFuncSetAttribute(hgemm<false>, cudaFuncAttributeMaxDynamicSharedMemorySize, SMEM_TOTAL);

    __half *Ah, *W, *Xh;
    cudaGetSymbolAddress((void**)&Ah, g_Ah);
    cudaGetSymbolAddress((void**)&W,  g_W);
    cudaGetSymbolAddress((void**)&Xh, g_Xh);

    // 1) Ah = fp16(A)  (upper-tri blocks + smem transpose, all coalesced)
    build_Ah_sym<<<dim3(DIM / 32, DIM / 32), 256>>>(angles);

    // 2) W = I + 2A + A@A  (HMMA, fused epilogue)  ++  fused X->fp16 converter
    //    grid.x = 16 GEMM blocks + 16 converter columns (x gridDim.y = 256 conv CTAs)
    hgemm<true><<<dim3(GEMM_NX + NCONV / (DIM / BM), DIM / BM), THREADS, SMEM_TOTAL>>>(
        Ah, Ah, nullptr, angles, nullptr, x);

    // 3) out = Xh @ W + bias
    hgemm<false><<<dim3(DIM / BN, MBIG / BM), THREADS, SMEM_TOTAL>>>(
        Xh, W, out, nullptr, bias, nullptr);
}

// round 17
// speedup vs baseline: 1.0333x; 1.0307x over previous
#include <cuda_runtime.h>
#include <cuda_fp16.h>
#include <cstdint>

#define DIM 2048
constexpr int MBIG  = 16384;           // 4*4096 tokens
constexpr int BM = 128, BN = 128, BK = 64;
constexpr int STAGES = 3;
constexpr int THREADS = 256;
constexpr int NITER = DIM / BK;        // 32 k-chunks
constexpr int STG_A = BM * 128;        // 16384 B (128 rows x 128B)
constexpr int STG_B = BK * 256;        // 16384 B (64 rows x 256B)
constexpr int STGB  = STG_A + STG_B;   // 32768 B per stage
constexpr int SMEM_TOTAL = STAGES * STGB;  // 98304 B  (2 CTAs/SM)

// ---------------- device scratch (no allocs allowed) ----------------
__device__ __half g_Ah[(size_t)DIM * DIM];   // fp16(A)
__device__ __half g_W [(size_t)DIM * DIM];   // fp16(I + 2A + A^2), [k][n]
__device__ __half g_Xh[(size_t)MBIG * DIM];  // fp16(X)

// ---------------- PTX helpers ----------------
__device__ __forceinline__ uint32_t smem_u32(const void* p) {
    uint32_t a;
    asm("{ .reg .u64 t; cvta.to.shared.u64 t, %1; cvt.u32.u64 %0, t; }" : "=r"(a) : "l"(p));
    return a;
}
#define CP_ASYNC_16(dst, src) \
    asm volatile("cp.async.cg.shared.global [%0], [%1], 16;" :: "r"(dst), "l"(src) : "memory")
#define CP_COMMIT() asm volatile("cp.async.commit_group;" ::: "memory")
#define CP_WAIT_1() asm volatile("cp.async.wait_group 1;" ::: "memory")
#define CP_WAIT_0() asm volatile("cp.async.wait_group 0;" ::: "memory")

__device__ __forceinline__ void ldsm_x4(uint32_t* r, uint32_t addr) {
    asm volatile("ldmatrix.sync.aligned.m8n8.x4.shared.b16 {%0,%1,%2,%3}, [%4];"
                 : "=r"(r[0]), "=r"(r[1]), "=r"(r[2]), "=r"(r[3]) : "r"(addr));
}
__device__ __forceinline__ void ldsm_x4t(uint32_t* r, uint32_t addr) {
    asm volatile("ldmatrix.sync.aligned.m8n8.x4.trans.shared.b16 {%0,%1,%2,%3}, [%4];"
                 : "=r"(r[0]), "=r"(r[1]), "=r"(r[2]), "=r"(r[3]) : "r"(addr));
}
__device__ __forceinline__ void mma16816(float* c, const uint32_t* a, const uint32_t* b) {
    asm volatile(
        "mma.sync.aligned.m16n8k16.row.col.f32.f16.f16.f32 "
        "{%0,%1,%2,%3}, {%4,%5,%6,%7}, {%8,%9}, {%0,%1,%2,%3};"
        : "+f"(c[0]), "+f"(c[1]), "+f"(c[2]), "+f"(c[3])
        : "r"(a[0]), "r"(a[1]), "r"(a[2]), "r"(a[3]), "r"(b[0]), "r"(b[1]));
}

// ---------------- build kernels ----------------
__device__ __forceinline__ float skew_entry(const float* __restrict__ angles, int i, int j) {
    if (i == j) return 0.0f;
    if (i < j)  return  angles[i * (2 * DIM - i - 1) / 2 + (j - i - 1)];
    return -angles[j * (2 * DIM - j - 1) / 2 + (i - j - 1)];
}

// Upper-triangle-block version: block (bi,bj) with bi<=bj computes the 32x32
// tile from coalesced angles reads and writes both the tile and its negated
// transpose (through an smem tile). Blocks with bi>bj exit immediately.
__global__ void build_Ah_sym(const float* __restrict__ angles) {
    int bi = blockIdx.y, bj = blockIdx.x;
    if (bi > bj) return;
    __shared__ float tile[32][33];
    int t = threadIdx.x;
    int tr = t >> 3;            // 0..31 row within tile
    int tc = (t & 7) * 4;       // 0..28 col group within tile
    int i0 = bi * 32, j0 = bj * 32;
    int i = i0 + tr;
    float v[4];
    #pragma unroll
    for (int q = 0; q < 4; q++) {
        int j = j0 + tc + q;
        v[q] = skew_entry(angles, i, j);   // bi<bj: all coalesced upper reads
        tile[tr][tc + q] = v[q];
    }
    // direct store (row-major, coalesced 8B per thread)
    {
        __half2 h0 = __floats2half2_rn(v[0], v[1]);
        __half2 h1 = __floats2half2_rn(v[2], v[3]);
        __half2* p = (__half2*)&g_Ah[(size_t)i * DIM + j0 + tc];
        p[0] = h0; p[1] = h1;
    }
    __syncthreads();
    // transposed store: g_Ah[j][i] = -tile[i-i0][j-j0]
    {
        int jr = j0 + tr;                // output row
        float w[4];
        #pragma unroll
        for (int q = 0; q < 4; q++)
            w[q] = -tile[tc + q][tr];
        __half2 h0 = __floats2half2_rn(w[0], w[1]);
        __half2 h1 = __floats2half2_rn(w[2], w[3]);
        __half2* p = (__half2*)&g_Ah[(size_t)jr * DIM + i0 + tc];
        p[0] = h0; p[1] = h1;
    }
}

__global__ void build_Xh(const float* __restrict__ x) {
    size_t f = (size_t)blockIdx.x * blockDim.x + threadIdx.x;  // float4 index
    float4 v = *(const float4*)(x + f * 4);
    __half2 h0 = __floats2half2_rn(v.x, v.y);
    __half2 h1 = __floats2half2_rn(v.z, v.w);
    *(__half2*)(&g_Xh[f * 4])     = h0;
    *(__half2*)(&g_Xh[f * 4 + 2]) = h1;
}

// ---------------- fp16 HMMA GEMM ----------------
// acc[m,n] = sum_k Ag[m,k] * Bg[k,n]
// WEPI=false: outf[m,n] = acc + bias[n]
// WEPI=true : g_W[m,n]  = fp16(acc + 2*A[m,n] + (m==n))   (A from angles)
__device__ __forceinline__ void load_tile(
    uint32_t sA, uint32_t sB,
    const __half* __restrict__ Ag, const __half* __restrict__ Bg,
    int m0, int n0, int k0, int tid)
{
    const char* ap = (const char*)(Ag + (size_t)m0 * DIM + k0);
    #pragma unroll
    for (int it = 0; it < 4; it++) {            // A: 128 rows x 8 chunks(16B)
        int idx = tid + it * THREADS;
        int m = idx >> 3, c = idx & 7;
        CP_ASYNC_16(sA + m * 128 + ((c * 16) ^ ((m & 7) * 16)),
                    ap + (size_t)m * (DIM * 2) + c * 16);
    }
    const char* bp = (const char*)(Bg + (size_t)k0 * DIM + n0);
    #pragma unroll
    for (int it = 0; it < 4; it++) {            // B: 64 rows x 16 chunks(16B)
        int idx = tid + it * THREADS;
        int k = idx >> 4, c = idx & 15;
        CP_ASYNC_16(sB + k * 256 + ((c * 16) ^ ((k & 7) * 16)),
                    bp + (size_t)k * (DIM * 2) + c * 16);
    }
}

template <bool WEPI>
__global__ __launch_bounds__(THREADS, 2)
void hgemm(const __half* __restrict__ Ag, const __half* __restrict__ Bg,
           float* __restrict__ outf, const float* __restrict__ angles,
           const float* __restrict__ bias)
{
    extern __shared__ char smem[];
    uint32_t sb = smem_u32(smem);
    int tid = threadIdx.x, lane = tid & 31, wid = tid >> 5;
    int wm = (wid >> 2) * 64;     // warp row offset within CTA (0 or 64)
    int wn = (wid & 3) * 32;      // warp col offset within CTA (0..96)
    int m0 = blockIdx.y * BM, n0 = blockIdx.x * BN;

    float acc[4][4][4];
    #pragma unroll
    for (int i = 0; i < 4; i++)
        #pragma unroll
        for (int j = 0; j < 4; j++)
            #pragma unroll
            for (int q = 0; q < 4; q++)
                acc[i][j][q] = 0.0f;

    // prologue: stages 0..STAGES-2
    #pragma unroll
    for (int s = 0; s < STAGES - 1; s++) {
        uint32_t sA = sb + s * STGB;
        load_tile(sA, sA + STG_A, Ag, Bg, m0, n0, s * BK, tid);
        CP_COMMIT();
    }

    for (int c = 0; c < NITER; c++) {
        int st = c % STAGES;
        uint32_t sA = sb + st * STGB;
        uint32_t sB = sA + STG_A;

        if (c + 1 < NITER) { CP_WAIT_1(); } else { CP_WAIT_0(); }
        __syncthreads();

        // ---- compute FIRST: tensor pipe refills immediately post-barrier ----
        #pragma unroll
        for (int ks = 0; ks < 4; ks++) {        // 4 x k16 within BK=64
            uint32_t a[4][4];
            uint32_t b[4][2];
            // A frags: m16k16 via ldmatrix.x4
            {
                int rbase = wm + (lane & 15);
                int kb = ks * 32 + (lane >> 4) * 16;
                #pragma unroll
                for (int mi = 0; mi < 4; mi++) {
                    int r = rbase + mi * 16;
                    ldsm_x4(a[mi], sA + r * 128 + (kb ^ ((r & 7) * 16)));
                }
            }
            // B frags: k16n16 via ldmatrix.x4.trans -> two n8 frags each
            {
                int grp = lane >> 3;
                int kk = ks * 16 + (grp & 1) * 8 + (lane & 7);
                int nbase = (wn + (grp >> 1) * 8) * 2;
                uint32_t rowa = sB + kk * 256;
                int kx = (kk & 7) * 16;
                #pragma unroll
                for (int nj = 0; nj < 2; nj++) {
                    uint32_t r4[4];
                    ldsm_x4t(r4, rowa + ((nbase + nj * 32) ^ kx));
                    b[nj * 2][0] = r4[0]; b[nj * 2][1] = r4[1];
                    b[nj * 2 + 1][0] = r4[2]; b[nj * 2 + 1][1] = r4[3];
                }
            }
            #pragma unroll
            for (int mi = 0; mi < 4; mi++)
                #pragma unroll
                for (int nf = 0; nf < 4; nf++)
                    mma16816(acc[mi][nf], a[mi], b[nf]);
        }

        // ---- then issue next-stage loads (overwrites stage (c+2)%3, which
        //      warps last read at chunk c-1; protected by this chunk's barrier)
        if (c + STAGES - 1 < NITER) {
            int st2 = (c + STAGES - 1) % STAGES;
            uint32_t nA = sb + st2 * STGB;
            load_tile(nA, nA + STG_A, Ag, Bg, m0, n0, (c + STAGES - 1) * BK, tid);
            CP_COMMIT();
        }
    }

    // epilogue
    int rbase = m0 + wm + (lane >> 2);
    int cbase = n0 + wn + (lane & 3) * 2;
    #pragma unroll
    for (int mi = 0; mi < 4; mi++) {
        #pragma unroll
        for (int nf = 0; nf < 4; nf++) {
            int r = rbase + mi * 16;
            int col = cbase + nf * 8;
            if (WEPI) {
                // W[r][col] = acc + 2*A[r][col] + (r==col), fp16
                #pragma unroll
                for (int h = 0; h < 2; h++) {
                    int rr = r + h * 8;
                    float w0 = acc[mi][nf][h * 2 + 0]
                             + 2.0f * skew_entry(angles, rr, col)
                             + (rr == col ? 1.0f : 0.0f);
                    float w1 = acc[mi][nf][h * 2 + 1]
                             + 2.0f * skew_entry(angles, rr, col + 1)
                             + (rr == col + 1 ? 1.0f : 0.0f);
                    *(__half2*)(&g_W[(size_t)rr * DIM + col]) =
                        __floats2half2_rn(w0, w1);
                }
            } else {
                float2 bv = *(const float2*)(bias + col);
                float2 v0 = make_float2(acc[mi][nf][0] + bv.x, acc[mi][nf][1] + bv.y);
                float2 v1 = make_float2(acc[mi][nf][2] + bv.x, acc[mi][nf][3] + bv.y);
                *(float2*)(outf + (size_t)r * DIM + col) = v0;
                *(float2*)(outf + (size_t)(r + 8) * DIM + col) = v1;
            }
        }
    }
}

// ---------------- launch ----------------
extern "C" void kernel_launch(void* const* d_in, const int* in_sizes, int n_in,
                              void* d_out, int out_size) {
    const float* x      = (const float*)d_in[0];   // [4,4096,2048]
    const float* angles = (const float*)d_in[1];
    const float* bias   = (const float*)d_in[2];
    float* out          = (float*)d_out;

    cudaFuncSetAttribute(hgemm<true>,  cudaFuncAttributeMaxDynamicSharedMemorySize, SMEM_TOTAL);
    cudaFuncSetAttribute(hgemm<false>, cudaFuncAttributeMaxDynamicSharedMemorySize, SMEM_TOTAL);

    __half *Ah, *W, *Xh;
    cudaGetSymbolAddress((void**)&Ah, g_Ah);
    cudaGetSymbolAddress((void**)&W,  g_W);
    cudaGetSymbolAddress((void**)&Xh, g_Xh);

    // 1) Ah = fp16(A)  (upper-tri blocks + smem transpose, all coalesced)
    build_Ah_sym<<<dim3(DIM / 32, DIM / 32), 256>>>(angles);
    // 2) W = I + 2A + A@A  (HMMA, fused epilogue, fp16 out)
    hgemm<true><<<dim3(DIM / BN, DIM / BM), THREADS, SMEM_TOTAL>>>(
        Ah, Ah, nullptr, angles, nullptr);
    // 3) Xh = fp16(X)
    build_Xh<<<(size_t)MBIG * DIM / 4 / 256, 256>>>(x);
    // 4) out = Xh @ W + bias
    hgemm<false><<<dim3(DIM / BN, MBIG / BM), THREADS, SMEM_TOTAL>>>(
        Xh, W, out, nullptr, bias);
}